// round 5
// baseline (speedup 1.0000x reference)
#include <cuda_runtime.h>

#define MAX_N 20000
#define MAX_E 640000

// Scratch (device globals; no allocation allowed)
__device__ float4 g_h4[MAX_N * 128];      // h[n][o*4+t], float4 view: [n][128]
__device__ int g_deg[MAX_N];
__device__ int g_start[MAX_N + 1];
__device__ int g_cursor[MAX_N];
__device__ int g_srcs[MAX_E];

__device__ __forceinline__ int clampi(int v, int hi) {
    v = v < 0 ? 0 : v;
    return v > hi ? hi : v;
}

__global__ void init_kernel(int n) {
    int i = blockIdx.x * blockDim.x + threadIdx.x;
    if (i < n) g_deg[i] = 0;
}

// edge_index is int32 (JAX default x64-disabled downgrades int64 -> int32)
__global__ void hist_kernel(const int* __restrict__ dst, int E, int n) {
    int e = blockIdx.x * blockDim.x + threadIdx.x;
    if (e < E) atomicAdd(&g_deg[clampi(dst[e], n - 1)], 1);
}

// Single-block exclusive scan over g_deg -> g_start, g_cursor. 1024 threads.
__global__ void scan_kernel(int n) {
    __shared__ int warpsum[32];
    __shared__ int carry_s;
    const int tid = threadIdx.x;
    const int lane = tid & 31, w = tid >> 5;
    if (tid == 0) carry_s = 0;
    __syncthreads();
    int nChunks = (n + 1023) >> 10;
    for (int c = 0; c < nChunks; ++c) {
        int i = (c << 10) + tid;
        int v = (i < n) ? g_deg[i] : 0;
        int base = carry_s;
        int x = v;
#pragma unroll
        for (int off = 1; off < 32; off <<= 1) {
            int y = __shfl_up_sync(0xffffffffu, x, off);
            if (lane >= off) x += y;
        }
        if (lane == 31) warpsum[w] = x;
        __syncthreads();
        if (w == 0) {
            int s = warpsum[lane];
#pragma unroll
            for (int off = 1; off < 32; off <<= 1) {
                int y = __shfl_up_sync(0xffffffffu, s, off);
                if (lane >= off) s += y;
            }
            warpsum[lane] = s;
        }
        __syncthreads();
        int wbase = (w == 0) ? 0 : warpsum[w - 1];
        int incl = x + wbase;
        int excl = base + incl - v;
        if (i < n) { g_start[i] = excl; g_cursor[i] = excl; }
        __syncthreads();
        if (tid == 1023) carry_s = base + incl;
        __syncthreads();
    }
    if (tid == 0) g_start[n] = carry_s;
}

__global__ void fill_kernel(const int* __restrict__ src,
                            const int* __restrict__ dst, int E, int n) {
    int e = blockIdx.x * blockDim.x + threadIdx.x;
    if (e < E) {
        int d = clampi(dst[e], n - 1);
        int pos = atomicAdd(&g_cursor[d], 1);
        if (pos < MAX_E) g_srcs[pos] = clampi(src[e], n - 1);
    }
}

// h[n][o*4+t] = sum_f x[n][f][t] * W[o][f] + b[o]
// Block: 128 threads = 4 warps, each warp handles one node of a group of 4.
// blockIdx.y selects o-half [0,64) or [64,128). W transposed in smem.
__global__ void __launch_bounds__(128) gemm_kernel(
    const float4* __restrict__ x4, const float* __restrict__ W,
    const float* __restrict__ b, int nNodes) {
    __shared__ float wt[128 * 68];    // wt[f*68 + j], j = o - o_base
    __shared__ float4 xs[4][128];     // 4 nodes x 128 float4 (512 floats each)
    const int tid = threadIdx.x;
    const int o_base = blockIdx.y << 6;

    // Load W transposed: step c reads W[o_base+c][tid] (coalesced)
    for (int c = 0; c < 64; ++c)
        wt[tid * 68 + c] = W[(o_base + c) * 128 + tid];

    const int wrp = tid >> 5, l = tid & 31;
    const float bo0 = b[o_base + 2 * l];
    const float bo1 = b[o_base + 2 * l + 1];

    int nGroups = (nNodes + 3) >> 2;
    for (int g = blockIdx.x; g < nGroups; g += gridDim.x) {
        int n0 = g << 2;
        __syncthreads();  // also orders wt writes before first read
        // Stage 4 nodes: 4 x 128 float4 = 512 float4 total, 4 iters x 128 thr
#pragma unroll
        for (int k = 0; k < 4; ++k) {
            int i = (k << 7) + tid;       // 0..511
            int node = i >> 7, off = i & 127;
            if (n0 + node < nNodes)
                (&xs[0][0])[i] = x4[(n0 + node) * 128 + off];
        }
        __syncthreads();
        int n = n0 + wrp;
        if (n < nNodes) {
            float4 a0 = make_float4(bo0, bo0, bo0, bo0);
            float4 a1 = make_float4(bo1, bo1, bo1, bo1);
            const float4* xr = xs[wrp];
#pragma unroll 4
            for (int f = 0; f < 128; ++f) {
                float4 xv = xr[f];
                float2 wv = *(const float2*)(wt + f * 68 + 2 * l);
                a0.x = fmaf(xv.x, wv.x, a0.x);
                a0.y = fmaf(xv.y, wv.x, a0.y);
                a0.z = fmaf(xv.z, wv.x, a0.z);
                a0.w = fmaf(xv.w, wv.x, a0.w);
                a1.x = fmaf(xv.x, wv.y, a1.x);
                a1.y = fmaf(xv.y, wv.y, a1.y);
                a1.z = fmaf(xv.z, wv.y, a1.z);
                a1.w = fmaf(xv.w, wv.y, a1.w);
            }
            // float offset n*512 + (o_base+2l)*4 -> float4: n*128 + o_base + 2l
            float4* hp = g_h4 + n * 128 + o_base + 2 * l;
            hp[0] = a0;
            hp[1] = a1;
        }
    }
}

__device__ __forceinline__ float4 fmax4(float4 a, float4 b) {
    return make_float4(fmaxf(a.x, b.x), fmaxf(a.y, b.y),
                       fmaxf(a.z, b.z), fmaxf(a.w, b.w));
}

// One warp per dst node. Thread l owns 16 floats (4 float4) of the 512-float row.
// Mainloop: 4 edges/iter -> deep MLP to hide ~240cyc L2 latency.
__global__ void gather_kernel(float4* __restrict__ out4, int nNodes) {
    int gw = (int)((blockIdx.x * blockDim.x + threadIdx.x) >> 5);
    int l = threadIdx.x & 31;
    if (gw >= nNodes) return;
    int s0 = g_start[gw], s1 = g_start[gw + 1];
    float4* op = out4 + gw * 128 + l * 4;
    if (s0 == s1) {
        float4 z = make_float4(0.f, 0.f, 0.f, 0.f);
        op[0] = z; op[1] = z; op[2] = z; op[3] = z;
        return;
    }
    const float NI = -__int_as_float(0x7f800000);  // -inf
    float4 m0 = make_float4(NI, NI, NI, NI), m1 = m0, m2 = m0, m3 = m0;
    const float4* hb = g_h4;
    int e = s0;
    for (; e + 4 <= s1; e += 4) {
        int sa = g_srcs[e],     sb = g_srcs[e + 1];
        int sc = g_srcs[e + 2], sd = g_srcs[e + 3];
        const float4* pa = hb + sa * 128 + l * 4;
        const float4* pb = hb + sb * 128 + l * 4;
        const float4* pc = hb + sc * 128 + l * 4;
        const float4* pd = hb + sd * 128 + l * 4;
        float4 A0 = pa[0], A1 = pa[1], A2 = pa[2], A3 = pa[3];
        float4 B0 = pb[0], B1 = pb[1], B2 = pb[2], B3 = pb[3];
        float4 C0 = pc[0], C1 = pc[1], C2 = pc[2], C3 = pc[3];
        float4 D0 = pd[0], D1 = pd[1], D2 = pd[2], D3 = pd[3];
        m0 = fmax4(m0, fmax4(fmax4(A0, B0), fmax4(C0, D0)));
        m1 = fmax4(m1, fmax4(fmax4(A1, B1), fmax4(C1, D1)));
        m2 = fmax4(m2, fmax4(fmax4(A2, B2), fmax4(C2, D2)));
        m3 = fmax4(m3, fmax4(fmax4(A3, B3), fmax4(C3, D3)));
    }
    for (; e < s1; ++e) {
        int sa = g_srcs[e];
        const float4* pa = hb + sa * 128 + l * 4;
        m0 = fmax4(m0, pa[0]);
        m1 = fmax4(m1, pa[1]);
        m2 = fmax4(m2, pa[2]);
        m3 = fmax4(m3, pa[3]);
    }
    op[0] = m0; op[1] = m1; op[2] = m2; op[3] = m3;
}

extern "C" void kernel_launch(void* const* d_in, const int* in_sizes, int n_in,
                              void* d_out, int out_size) {
    const float* x = (const float*)d_in[0];
    const int* ei = (const int*)d_in[1];      // int32! (JAX x64 disabled)
    const float* W = (const float*)d_in[2];
    const float* b = (const float*)d_in[3];
    float* out = (float*)d_out;

    int nNodes = in_sizes[0] / 512;   // F*T = 128*4
    int E = in_sizes[1] / 2;

    const int* src = ei;          // edge_index[0], E int32 values
    const int* dst = ei + E;      // edge_index[1]

    init_kernel<<<(nNodes + 255) / 256, 256>>>(nNodes);
    hist_kernel<<<(E + 255) / 256, 256>>>(dst, E, nNodes);
    scan_kernel<<<1, 1024>>>(nNodes);
    fill_kernel<<<(E + 255) / 256, 256>>>(src, dst, E, nNodes);

    dim3 gg(370, 2);
    gemm_kernel<<<gg, 128>>>((const float4*)x, W, b, nNodes);

    gather_kernel<<<(nNodes + 7) / 8, 256>>>((float4*)out, nNodes);
}